// round 4
// baseline (speedup 1.0000x reference)
#include <cuda_runtime.h>

#define BB 8192
#define HH 100
#define TT 512
#define NOPSN 5
#define ZW 400      // 4*H
#define RPW 7       // rows per warp
#define NWARP 8
#define RPB 56      // rows per block
#define NTHREADS 256

typedef unsigned long long u64t;

// Scratch
__device__ float g_xW0[(size_t)BB * ZW];   // x0 @ W_x, gate-interleaved cols
__device__ float g_embW[6 * ZW];           // emb @ W_x, gate-interleaved cols

// storage col j -> original col (j%4)*100 + j/4  (i,f,c,o interleave)
__device__ __host__ __forceinline__ int permCol(int j) {
    return (j & 3) * 100 + (j >> 2);
}

__device__ __forceinline__ float fsig(float x) {
    return __fdividef(1.f, 1.f + __expf(-x));
}
__device__ __forceinline__ float ftanh_(float x) {
    float e = __expf(2.f * x);
    return 1.f - __fdividef(2.f, e + 1.f);
}
__device__ __forceinline__ u64t ffma2(u64t a, u64t b, u64t c) {
    u64t d;
    asm("fma.rn.f32x2 %0, %1, %2, %3;" : "=l"(d) : "l"(a), "l"(b), "l"(c));
    return d;
}
__device__ __forceinline__ u64t pack2(float x) {
    unsigned int xi = __float_as_uint(x);
    u64t d;
    asm("mov.b64 %0, {%1, %2};" : "=l"(d) : "r"(xi), "r"(xi));
    return d;
}
__device__ __forceinline__ void unpk(u64t v, float& lo, float& hi) {
    unsigned int a, b;
    asm("mov.b64 {%0, %1}, %2;" : "=r"(a), "=r"(b) : "l"(v));
    lo = __uint_as_float(a); hi = __uint_as_float(b);
}

__global__ void embW_kernel(const float* __restrict__ emb, const float* __restrict__ Wx) {
    int j = threadIdx.x;
    if (j >= ZW) return;
    int pj = permCol(j);
    for (int e = 0; e < 6; ++e) {
        float acc = 0.f;
        #pragma unroll 4
        for (int k = 0; k < HH; ++k)
            acc = fmaf(emb[e * HH + k], Wx[k * ZW + pj], acc);
        g_embW[e * ZW + j] = acc;
    }
}

__global__ void xw0_kernel(const float* __restrict__ x0, const float* __restrict__ Wx) {
    __shared__ float xs[HH];
    int b = blockIdx.x;
    for (int i = threadIdx.x; i < HH; i += blockDim.x) xs[i] = x0[b * HH + i];
    __syncthreads();
    for (int j = threadIdx.x; j < ZW; j += blockDim.x) {
        int pj = permCol(j);
        float acc = 0.f;
        #pragma unroll 4
        for (int k = 0; k < HH; ++k) acc = fmaf(xs[k], Wx[k * ZW + pj], acc);
        g_xW0[(size_t)b * ZW + j] = acc;
    }
}

__global__ void __launch_bounds__(NTHREADS, 1)
rnn_main(const float* __restrict__ Wh, const float* __restrict__ Wops,
         const float* __restrict__ u, float* __restrict__ out)
{
    extern __shared__ float sm[];
    float* sWh  = sm;                        // [100][400] gate-interleaved
    float* sEmb = sWh + HH * ZW;             // [6][400]   gate-interleaved
    u64t*  sH2  = (u64t*)(sEmb + 6 * ZW);    // [56][100]  (h,h) pairs

    const int tid = threadIdx.x, wid = tid >> 5, lane = tid & 31;
    const int odd = lane & 1, a2 = lane >> 1;
    const int odd16 = odd * 16;

    for (int i = tid; i < HH * ZW; i += NTHREADS) {
        int k = i / ZW, j = i - k * ZW;
        sWh[i] = Wh[k * ZW + permCol(j)];
    }
    for (int i = tid; i < 6 * ZW; i += NTHREADS) sEmb[i] = g_embW[i];
    for (int i = tid; i < RPB * HH; i += NTHREADS) sH2[i] = 0ull;
    __syncthreads();

    const int rowBlock = blockIdx.x * RPB;
    const int lrow0 = wid * RPW;
    const int gb0 = rowBlock + lrow0;

    // per-lane packed column offsets: pair (2*lane, 2*lane+1) + 64*s
    int c6 = (lane < 8) ? (2 * lane + 384) : 0;   // clamped; masked lanes discard

    // cell state: main units (3 per lane) per row + one tail unit
    float cS[RPW][3];
    #pragma unroll
    for (int r = 0; r < RPW; ++r)
        #pragma unroll
        for (int it = 0; it < 3; ++it) cS[r][it] = 0.f;
    float cTail = 0.f;

    // W_ops rows for this lane's units
    float wopsr[3][NOPSN], wopsT[NOPSN];
    #pragma unroll
    for (int it = 0; it < 3; ++it) {
        int uu = a2 + 32 * it + odd16;   // < 96
        #pragma unroll
        for (int n = 0; n < NOPSN; ++n) wopsr[it][n] = Wops[uu * NOPSN + n];
    }
    {
        int uu = 96 + (lane & 3);
        #pragma unroll
        for (int n = 0; n < NOPSN; ++n) wopsT[n] = Wops[uu * NOPSN + n];
    }

    const int rT = lane >> 2, aT = lane & 3;
    const bool tActive = (rT < RPW);

    float accLP = 0.f, accENT = 0.f;
    int opReg = 0;

    for (int t = 0; t < TT; ++t) {
        // gumbel inputs (lanes 0..6 own rows)
        float un[NOPSN] = {0.f, 0.f, 0.f, 0.f, 0.f};
        {
            int b = gb0 + lane;
            if (lane < RPW && b < BB) {
                const float* up = u + ((size_t)t * BB + b) * NOPSN;
                #pragma unroll
                for (int n = 0; n < NOPSN; ++n) un[n] = up[n];
            }
        }

        // ---- init z accumulators ----
        u64t z[RPW][7];
        if (t == 0) {
            #pragma unroll
            for (int r = 0; r < RPW; ++r) {
                int bb = gb0 + r; if (bb >= BB) bb = BB - 1;
                const float* xp = g_xW0 + (size_t)bb * ZW;
                #pragma unroll
                for (int s = 0; s < 6; ++s)
                    z[r][s] = *(const u64t*)(xp + 2 * lane + 64 * s);
                z[r][6] = *(const u64t*)(xp + c6);
            }
        } else {
            #pragma unroll
            for (int r = 0; r < RPW; ++r) {
                int orr = __shfl_sync(0xffffffffu, opReg, r);
                const float* ep = sEmb + orr * ZW;
                #pragma unroll
                for (int s = 0; s < 6; ++s)
                    z[r][s] = *(const u64t*)(ep + 2 * lane + 64 * s);
                z[r][6] = *(const u64t*)(ep + c6);
            }
        }

        // ---- h @ W_h mainloop ----
        const u64t* hRow = sH2 + lrow0 * HH;
        #pragma unroll 2
        for (int k = 0; k < HH; ++k) {
            const float* wk = sWh + k * ZW;
            u64t w[7];
            #pragma unroll
            for (int s = 0; s < 6; ++s) w[s] = *(const u64t*)(wk + 2 * lane + 64 * s);
            w[6] = *(const u64t*)(wk + c6);
            u64t hp[RPW];
            #pragma unroll
            for (int r = 0; r < RPW; ++r) hp[r] = hRow[r * HH + k];
            #pragma unroll
            for (int s = 0; s < 7; ++s) {
                #pragma unroll
                for (int r = 0; r < RPW; ++r)
                    z[r][s] = ffma2(hp[r], w[s], z[r][s]);
            }
        }

        // ---- tail: units 96..99 for all 7 rows in one pass ----
        float plT[NOPSN] = {0.f, 0.f, 0.f, 0.f, 0.f};
        {
            u64t IFt = 0, COt = 0;
            #pragma unroll
            for (int rr = 0; rr < RPW; ++rr) {
                u64t vIF = __shfl_sync(0xffffffffu, z[rr][6], 2 * aT);
                u64t vCO = __shfl_sync(0xffffffffu, z[rr][6], 2 * aT + 1);
                if (rT == rr) { IFt = vIF; COt = vCO; }
            }
            float zi, zf, zc, zo;
            unpk(IFt, zi, zf); unpk(COt, zc, zo);
            float cn = fsig(zf) * cTail + fsig(zi) * ftanh_(zc);
            cTail = cn;
            float hn = fsig(zo) * ftanh_(cn);
            if (tActive) {
                sH2[(lrow0 + rT) * HH + 96 + aT] = pack2(hn);
                #pragma unroll
                for (int n = 0; n < NOPSN; ++n) plT[n] = hn * wopsT[n];
            }
        }

        // ---- rows: gates for units 0..95 in registers + logit reduction ----
        float sums[NOPSN];
        #pragma unroll
        for (int r = 0; r < RPW; ++r) {
            u64t oth[6];
            #pragma unroll
            for (int s = 0; s < 6; ++s)
                oth[s] = __shfl_xor_sync(0xffffffffu, z[r][s], 1);

            float pl[NOPSN] = {0.f, 0.f, 0.f, 0.f, 0.f};
            #pragma unroll
            for (int it = 0; it < 3; ++it) {
                u64t IF = odd ? oth[2 * it + 1] : z[r][2 * it];
                u64t CO = odd ? z[r][2 * it + 1] : oth[2 * it];
                float zi, zf, zc, zo;
                unpk(IF, zi, zf); unpk(CO, zc, zo);
                float cn = fsig(zf) * cS[r][it] + fsig(zi) * ftanh_(zc);
                cS[r][it] = cn;
                float hn = fsig(zo) * ftanh_(cn);
                int uu = a2 + 32 * it + odd16;
                sH2[(lrow0 + r) * HH + uu] = pack2(hn);
                #pragma unroll
                for (int n = 0; n < NOPSN; ++n)
                    pl[n] = fmaf(hn, wopsr[it][n], pl[n]);
            }
            // fold tail contribution for this row, then butterfly-reduce
            #pragma unroll
            for (int n = 0; n < NOPSN; ++n)
                pl[n] += (rT == r) ? plT[n] : 0.f;
            #pragma unroll
            for (int off = 16; off; off >>= 1) {
                #pragma unroll
                for (int n = 0; n < NOPSN; ++n)
                    pl[n] += __shfl_xor_sync(0xffffffffu, pl[n], off);
            }
            if (lane == r) {
                #pragma unroll
                for (int n = 0; n < NOPSN; ++n) sums[n] = pl[n];
            }
        }

        // ---- sampling / log-softmax epilogue (fast intrinsics) ----
        if (lane < RPW) {
            int b = gb0 + lane;
            if (b < BB) {
                float lg[NOPSN];
                #pragma unroll
                for (int n = 0; n < NOPSN; ++n) lg[n] = 1.5f * ftanh_(sums[n]);
                int op = 0;
                float best = 0.f, m = lg[0], lgsel = lg[0];
                #pragma unroll
                for (int n = 0; n < NOPSN; ++n) {
                    float gum = -__logf(-__logf(un[n] + 1e-9f) + 1e-9f);
                    float v = lg[n] + gum;
                    if (n == 0) { best = v; }
                    else if (v > best) { best = v; op = n; lgsel = lg[n]; }
                    if (lg[n] > m) m = lg[n];
                }
                float ssum = 0.f;
                #pragma unroll
                for (int n = 0; n < NOPSN; ++n) ssum += __expf(lg[n] - m);
                float lse = m + __logf(ssum);
                float cur = lse - lgsel;
                float ent = cur * __expf(-cur);
                accLP += cur;
                accENT += ent;
                opReg = op;
                out[2 * (size_t)BB + (size_t)t * BB + b] = (float)op;
            }
        }
        __syncwarp();
    }

    if (lane < RPW) {
        int b = gb0 + lane;
        if (b < BB) {
            out[b] = accLP;
            out[BB + b] = accENT;
        }
    }
}

extern "C" void kernel_launch(void* const* d_in, const int* in_sizes, int n_in,
                              void* d_out, int out_size) {
    const float* x0  = (const float*)d_in[0];
    const float* Wx  = (const float*)d_in[1];
    const float* Wh  = (const float*)d_in[2];
    const float* Wop = (const float*)d_in[3];
    const float* emb = (const float*)d_in[4];
    const float* u   = (const float*)d_in[5];
    float* out = (float*)d_out;

    size_t smem = (size_t)(HH * ZW + 6 * ZW) * sizeof(float) + (size_t)RPB * HH * sizeof(u64t);
    cudaFuncSetAttribute(rnn_main, cudaFuncAttributeMaxDynamicSharedMemorySize, (int)smem);

    embW_kernel<<<1, ZW>>>(emb, Wx);
    xw0_kernel<<<BB, 128>>>(x0, Wx);
    int grid = (BB + RPB - 1) / RPB;   // 147 blocks, one wave on 148 SMs
    rnn_main<<<grid, NTHREADS, smem>>>(Wh, Wop, u, out);
}

// round 5
// speedup vs baseline: 1.2516x; 1.2516x over previous
#include <cuda_runtime.h>

#define BB 8192
#define HH 100
#define TT 512
#define NOPSN 5
#define ZW 400      // 4*H
#define EW 448      // padded width for emb@Wx rows (7*64)
#define RPW 7       // rows per warp
#define NWARP 8
#define RPB 56      // rows per block
#define NTHREADS 256

typedef unsigned long long u64t;

// Scratch (static device allocations are allowed)
__device__ float g_xW0[(size_t)BB * ZW];   // x0 @ W_x   [B,400]
__device__ float g_embW[6 * EW];           // emb @ W_x  [6,448] (cols >=400 zero)

__device__ __forceinline__ float tanha(float x) {
    float y;
    asm("tanh.approx.f32 %0, %1;" : "=f"(y) : "f"(x));
    return y;
}
__device__ __forceinline__ float fsig(float x) {
    return fmaf(0.5f, tanha(0.5f * x), 0.5f);
}
__device__ __forceinline__ float ftanh_(float x) {
    return tanha(x);
}
// packed fp32x2 FMA: d = a*b + c (elementwise on the two f32 halves)
__device__ __forceinline__ u64t ffma2(u64t a, u64t b, u64t c) {
    u64t d;
    asm("fma.rn.f32x2 %0, %1, %2, %3;" : "=l"(d) : "l"(a), "l"(b), "l"(c));
    return d;
}
__device__ __forceinline__ u64t pack2(float x) {
    unsigned int xi = __float_as_uint(x);
    u64t d;
    asm("mov.b64 %0, {%1, %2};" : "=l"(d) : "r"(xi), "r"(xi));
    return d;
}

__global__ void embW_kernel(const float* __restrict__ emb, const float* __restrict__ Wx) {
    int j = threadIdx.x;
    if (j >= EW) return;
    for (int e = 0; e < 6; ++e) {
        float acc = 0.f;
        if (j < ZW) {
            #pragma unroll 4
            for (int k = 0; k < HH; ++k)
                acc = fmaf(emb[e * HH + k], Wx[k * ZW + j], acc);
        }
        g_embW[e * EW + j] = acc;
    }
}

__global__ void xw0_kernel(const float* __restrict__ x0, const float* __restrict__ Wx) {
    __shared__ float xs[HH];
    int b = blockIdx.x;
    for (int i = threadIdx.x; i < HH; i += blockDim.x) xs[i] = x0[b * HH + i];
    __syncthreads();
    for (int j = threadIdx.x; j < ZW; j += blockDim.x) {
        float acc = 0.f;
        #pragma unroll 4
        for (int k = 0; k < HH; ++k) acc = fmaf(xs[k], Wx[k * ZW + j], acc);
        g_xW0[(size_t)b * ZW + j] = acc;
    }
}

__global__ void __launch_bounds__(NTHREADS, 1)
rnn_main(const float* __restrict__ Wh, const float* __restrict__ Wops,
         const float* __restrict__ u, float* __restrict__ out)
{
    extern __shared__ float sm[];
    float* sWh  = sm;                      // [100][400] unpadded
    float* sEmb = sWh + HH * ZW;           // [6][448]
    float* sH   = sEmb + 6 * EW;           // [56][100]
    float* sZ   = sH + RPB * HH;           // [8][400] per-warp z scratch

    const int tid = threadIdx.x, wid = tid >> 5, lane = tid & 31;

    for (int i = tid; i < HH * ZW; i += NTHREADS) sWh[i] = Wh[i];
    for (int i = tid; i < 6 * EW; i += NTHREADS)  sEmb[i] = g_embW[i];
    for (int i = tid; i < RPB * HH; i += NTHREADS) sH[i] = 0.f;
    __syncthreads();

    const int rowBlock = blockIdx.x * RPB;
    const int lrow0 = wid * RPW;           // first row (in block) for this warp
    const int gb0 = rowBlock + lrow0;      // first global row for this warp

    float cS[RPW][4];
    #pragma unroll
    for (int r = 0; r < RPW; ++r)
        #pragma unroll
        for (int s = 0; s < 4; ++s) cS[r][s] = 0.f;

    float wopsr[4][NOPSN];
    #pragma unroll
    for (int s = 0; s < 4; ++s) {
        int unit = lane + 32 * s;
        #pragma unroll
        for (int n = 0; n < NOPSN; ++n)
            wopsr[s][n] = (unit < HH) ? Wops[unit * NOPSN + n] : 0.f;
    }

    // per-lane scalars: lane r (<7) owns row gb0+r
    float accLP = 0.f, accENT = 0.f;
    int opReg = 0;

    for (int t = 0; t < TT; ++t) {
        // ---- prefetch gumbel inputs for this warp's 7 rows ----
        float un[NOPSN] = {0.f, 0.f, 0.f, 0.f, 0.f};
        {
            int b = gb0 + lane;
            if (lane < RPW && b < BB) {
                const float* up = u + ((size_t)t * BB + b) * NOPSN;
                #pragma unroll
                for (int n = 0; n < NOPSN; ++n) un[n] = up[n];
            }
        }

        // ---- init z accumulators (pairs: lane handles j = 2*lane + 64*s) ----
        u64t z[RPW][7];
        if (t == 0) {
            #pragma unroll
            for (int r = 0; r < RPW; ++r) {
                int bb = gb0 + r; if (bb >= BB) bb = BB - 1;
                const float* xp = g_xW0 + (size_t)bb * ZW;
                #pragma unroll
                for (int s = 0; s < 7; ++s) {
                    int j = 2 * lane + 64 * s;
                    z[r][s] = (j < ZW) ? *(const u64t*)(xp + j) : 0ull;
                }
            }
        } else {
            #pragma unroll
            for (int r = 0; r < RPW; ++r) {
                int orr = __shfl_sync(0xffffffffu, opReg, r);
                const float* ep = sEmb + orr * EW;
                #pragma unroll
                for (int s = 0; s < 7; ++s)
                    z[r][s] = *(const u64t*)(ep + 2 * lane + 64 * s);
            }
        }

        // ---- h @ W_h mainloop: 7 rows share every weight load, packed FMA ----
        #pragma unroll 2
        for (int k = 0; k < HH; ++k) {
            u64t hp[RPW];
            #pragma unroll
            for (int r = 0; r < RPW; ++r)
                hp[r] = pack2(sH[(lrow0 + r) * HH + k]);
            const float* wrow = sWh + k * ZW + 2 * lane;
            #pragma unroll
            for (int s = 0; s < 7; ++s) {
                u64t w = *(const u64t*)(wrow + 64 * s);  // may over-read into sEmb pad; discarded lanes
                #pragma unroll
                for (int r = 0; r < RPW; ++r)
                    z[r][s] = ffma2(hp[r], w, z[r][s]);
            }
        }

        // ---- gates + logits per row ----
        float sums[NOPSN] = {0.f, 0.f, 0.f, 0.f, 0.f};
        float* zb = sZ + wid * ZW;

        #pragma unroll
        for (int r = 0; r < RPW; ++r) {
            #pragma unroll
            for (int s = 0; s < 7; ++s) {
                int j = 2 * lane + 64 * s;
                if (s < 6 || lane < 8) *(u64t*)(zb + j) = z[r][s];
            }
            __syncwarp();
            float pl[NOPSN] = {0.f, 0.f, 0.f, 0.f, 0.f};
            #pragma unroll
            for (int s2 = 0; s2 < 4; ++s2) {
                int unit = lane + 32 * s2;
                if (unit < HH) {
                    float zi = zb[unit];
                    float zf = zb[HH + unit];
                    float zc = zb[2 * HH + unit];
                    float zo = zb[3 * HH + unit];
                    float cn = fsig(zf) * cS[r][s2] + fsig(zi) * ftanh_(zc);
                    cS[r][s2] = cn;
                    float hn = fsig(zo) * ftanh_(cn);
                    sH[(lrow0 + r) * HH + unit] = hn;
                    #pragma unroll
                    for (int n = 0; n < NOPSN; ++n)
                        pl[n] = fmaf(hn, wopsr[s2][n], pl[n]);
                }
            }
            __syncwarp();
            #pragma unroll
            for (int off = 16; off; off >>= 1) {
                #pragma unroll
                for (int n = 0; n < NOPSN; ++n)
                    pl[n] += __shfl_xor_sync(0xffffffffu, pl[n], off);
            }
            if (lane == r) {
                #pragma unroll
                for (int n = 0; n < NOPSN; ++n) sums[n] = pl[n];
            }
        }

        // ---- sampling / log-softmax epilogue (fast intrinsics) ----
        if (lane < RPW) {
            int b = gb0 + lane;
            if (b < BB) {
                float lg[NOPSN];
                #pragma unroll
                for (int n = 0; n < NOPSN; ++n) lg[n] = 1.5f * tanha(sums[n]);
                int op = 0;
                float best = 0.f, m = lg[0], lgsel = lg[0];
                #pragma unroll
                for (int n = 0; n < NOPSN; ++n) {
                    float gum = -__logf(-__logf(un[n] + 1e-9f) + 1e-9f);
                    float v = lg[n] + gum;
                    if (n == 0) { best = v; }
                    else if (v > best) { best = v; op = n; lgsel = lg[n]; }
                    if (lg[n] > m) m = lg[n];
                }
                float ssum = 0.f;
                #pragma unroll
                for (int n = 0; n < NOPSN; ++n) ssum += __expf(lg[n] - m);
                float lse = m + __logf(ssum);
                float cur = lse - lgsel;          // -log_softmax(logits)[op]
                float ent = cur * __expf(-cur);
                accLP += cur;
                accENT += ent;
                opReg = op;
                out[2 * (size_t)BB + (size_t)t * BB + b] = (float)op;
            }
        }
        __syncwarp();
    }

    if (lane < RPW) {
        int b = gb0 + lane;
        if (b < BB) {
            out[b] = accLP;
            out[BB + b] = accENT;
        }
    }
}

extern "C" void kernel_launch(void* const* d_in, const int* in_sizes, int n_in,
                              void* d_out, int out_size) {
    const float* x0  = (const float*)d_in[0];
    const float* Wx  = (const float*)d_in[1];
    const float* Wh  = (const float*)d_in[2];
    const float* Wop = (const float*)d_in[3];
    const float* emb = (const float*)d_in[4];
    const float* u   = (const float*)d_in[5];
    float* out = (float*)d_out;

    size_t smem = (size_t)(HH * ZW + 6 * EW + RPB * HH + NWARP * ZW) * sizeof(float);
    cudaFuncSetAttribute(rnn_main, cudaFuncAttributeMaxDynamicSharedMemorySize, (int)smem);

    embW_kernel<<<1, EW>>>(emb, Wx);
    xw0_kernel<<<BB, 128>>>(x0, Wx);
    int grid = (BB + RPB - 1) / RPB;   // 147 blocks, one wave on 148 SMs
    rnn_main<<<grid, NTHREADS, smem>>>(Wh, Wop, u, out);
}